// round 15
// baseline (speedup 1.0000x reference)
#include <cuda_runtime.h>
#include <cuda_fp16.h>
#include <cstdint>
#include <math.h>

typedef unsigned int u32;

#define NIMG 512
#define IMG_ELEMS (64*64*32)

// ---- scratch (device globals; allocation-free rule) ----
__device__ __half g_x2h[67108864];      // conv output (+b3), fp16
__device__ float g_sh[NIMG*64*32];
__device__ float g_sw[NIMG*64*32];
__device__ float g_sum[NIMG*32];
__device__ float g_sumsq[NIMG*32];
__device__ float g_colsum[NIMG*32];
__device__ float g_mu[NIMG*32];
__device__ float g_rs[NIMG*32];
__device__ float g_x21[NIMG*32];
__device__ float g_x11[32];
// W transposed [d][k], fp16, row stride 328 halves (=656 B; ldmatrix conflict-free)
__device__ __align__(16) unsigned short g_whi[32*328];

// m16n8k16 row.col fp16 -> f32 accumulate (HMMA.16816; valid on base sm_103)
__device__ __forceinline__ void mma_f16(float* c, const u32* a, const u32* b) {
    asm volatile("mma.sync.aligned.m16n8k16.row.col.f32.f16.f16.f32 {%0,%1,%2,%3}, {%4,%5,%6,%7}, {%8,%9}, {%0,%1,%2,%3};" : "+f"(c[0]), "+f"(c[1]), "+f"(c[2]), "+f"(c[3]) : "r"(a[0]), "r"(a[1]), "r"(a[2]), "r"(a[3]), "r"(b[0]), "r"(b[1]));
}
__device__ __forceinline__ void ldsm_x4(u32* r, u32 saddr) {
    asm volatile("ldmatrix.sync.aligned.m8n8.x4.shared.b16 {%0,%1,%2,%3}, [%4];" : "=r"(r[0]), "=r"(r[1]), "=r"(r[2]), "=r"(r[3]) : "r"(saddr));
}
__device__ __forceinline__ u32 smem_u32(const void* p) {
    u32 a;
    asm("{ .reg .u64 t; cvta.to.shared.u64 t, %1; cvt.u32.u64 %0, t; }" : "=r"(a) : "l"(p));
    return a;
}

// ===================== K0: transpose conv weights to fp16 =====================
__global__ void k0_prep(const float* __restrict__ w3) {
    for (int idx = threadIdx.x; idx < 32*328; idx += blockDim.x) {
        int d = idx / 328;
        int k = idx % 328;
        float v = (k < 288) ? w3[k*32 + d] : 0.f;
        __half hb = __float2half_rn(v);
        g_whi[idx] = *(unsigned short*)&hb;
    }
}

// ===================== K1: row/col means + 32x32 matmul + sigmoid (+ zero stats) =====================
__global__ void __launch_bounds__(256) k1_means(const float* __restrict__ x,
                                                const float* __restrict__ w1,
                                                const float* __restrict__ b1) {
    int g = blockIdx.x;
    const float* A = x + (size_t)g * IMG_ELEMS;
    __shared__ float s_xh[2048];
    __shared__ float s_xw[2048];
    __shared__ float s_w1[1024];
    int tid = threadIdx.x;
    int lane = tid & 31;
    int wid = tid >> 5;

    if (tid < 32) {
        g_sum[g*32+tid] = 0.f;
        g_sumsq[g*32+tid] = 0.f;
        g_colsum[g*32+tid] = 0.f;
    }
    for (int i = tid; i < 1024; i += 256) s_w1[i] = w1[i];

    for (int h = wid; h < 64; h += 8) {
        float acc = 0.f;
        for (int w = 0; w < 64; w++) acc += A[(h*64 + w)*32 + lane];
        s_xh[h*32 + lane] = acc * (1.f/64.f);
    }
    for (int w = wid; w < 64; w += 8) {
        float acc = 0.f;
        for (int h = 0; h < 64; h++) acc += A[(h*64 + w)*32 + lane];
        s_xw[w*32 + lane] = acc * (1.f/64.f);
    }
    __syncthreads();
    for (int i = tid; i < 4096; i += 256) {
        int row = i >> 5;
        int d = i & 31;
        const float* v = (row < 64) ? (s_xh + row*32) : (s_xw + (row-64)*32);
        float acc = b1[d];
        for (int c = 0; c < 32; c++) acc = fmaf(v[c], s_w1[c*32 + d], acc);
        float s = 1.f / (1.f + expf(-acc));
        if (row < 64) g_sh[(g*64 + row)*32 + d] = s;
        else g_sw[(g*64 + (row-64))*32 + d] = s;
    }
}

// ===================== K2: fp16 HMMA conv, stats fused into fill =====================
// Block: 8 output rows x 64 cols x 32ch, 512 threads (16 warps; warp = 32-pixel strip).
// Halo 10/8 = 1.25x overread (was 1.5x). smem 90880 B -> 2 CTAs/SM (same 32 warps/SM).
#define SM_WH  0
#define SM_INH 20992
#define SM_RED 88576
#define SM_GN  90624
#define SM_TOTAL 90880
// input plane: [10 rows][66 cols][32 ci fp16], col stride 20 u32 (80 B); 52800 B
// s_out alias: 512 px * 33 f32 = 67584 B (region is max of the two)

__global__ void __launch_bounds__(512, 2) k2_conv(const float* __restrict__ x,
                                                  const float* __restrict__ b3) {
    int gimg = blockIdx.y;
    int h0 = blockIdx.x * 8;
    const float* A = x + (size_t)gimg * IMG_ELEMS;
    extern __shared__ char sm[];
    u32 smb = smem_u32(sm);
    u32* inh32 = (u32*)(sm + SM_INH);
    float* s_out = (float*)(sm + SM_INH);   // alias: valid only after all input reads; 67584 B
    float* s_red = (float*)(sm + SM_RED);
    float* s_gn  = (float*)(sm + SM_GN);    // [0..31] sum, [32..63] sumsq
    int tid = threadIdx.x;
    int lane = tid & 31;
    int wid = tid >> 5;

    if (tid < 64) s_gn[tid] = 0.f;
    // load W plane (pre-transposed fp16): 20992 B
    {
        const float4* srcH = (const float4*)g_whi;
        float4* dstH = (float4*)(sm + SM_WH);
        for (int i = tid; i < 1312; i += 512) dstH[i] = srcH[i];
    }

    // fill halo input tile (rows h0-1 .. h0+8) fp16; gated GN stats from fp32 inline.
    // ci base loop-invariant: (tid&7)*4 (512 % 8 == 0). No integer division.
    float s1v[4] = {0.f, 0.f, 0.f, 0.f};
    float s2v[4] = {0.f, 0.f, 0.f, 0.f};
    for (int r = 0; r < 10; r++) {
        int h = h0 - 1 + r;
        bool hok = (h >= 0 && h < 64);
        for (int j = tid; j < 528; j += 512) {     // 66 cols x 8 ci-chunks
            int col = j >> 3;
            int ci = (j & 7) * 4;
            bool inb = hok && col >= 1 && col <= 64;
            float4 v = make_float4(0.f, 0.f, 0.f, 0.f);
            if (inb) v = *(const float4*)(A + (h*64 + col - 1)*32 + ci);
            __half2 p01 = __floats2half2_rn(v.x, v.y);
            __half2 p23 = __floats2half2_rn(v.z, v.w);
            int wb = (r*66 + col)*20 + (ci >> 1);
            inh32[wb]     = *(u32*)&p01;
            inh32[wb + 1] = *(u32*)&p23;
            if (inb && r >= 1 && r <= 8) {
                float4 shv = *(const float4*)(g_sh + (gimg*64 + h)*32 + ci);
                float4 swv = *(const float4*)(g_sw + (gimg*64 + col - 1)*32 + ci);
                float g0 = v.x * shv.x * swv.x;
                float g1 = v.y * shv.y * swv.y;
                float g2 = v.z * shv.z * swv.z;
                float g3 = v.w * shv.w * swv.w;
                s1v[0] += g0; s2v[0] += g0*g0;
                s1v[1] += g1; s2v[1] += g1*g1;
                s1v[2] += g2; s2v[2] += g2*g2;
                s1v[3] += g3; s2v[3] += g3*g3;
            }
        }
    }
    __syncthreads();

    // reduce gated stats: lanes {l, l^8, l^16, l^24} share the same ci base
    #pragma unroll
    for (int j = 0; j < 4; j++) {
        s1v[j] += __shfl_xor_sync(0xffffffffu, s1v[j], 8);
        s1v[j] += __shfl_xor_sync(0xffffffffu, s1v[j], 16);
        s2v[j] += __shfl_xor_sync(0xffffffffu, s2v[j], 8);
        s2v[j] += __shfl_xor_sync(0xffffffffu, s2v[j], 16);
    }
    if (lane < 8) {
        int cib = (lane & 7) * 4;
        #pragma unroll
        for (int j = 0; j < 4; j++) {
            atomicAdd(s_gn + cib + j, s1v[j]);
            atomicAdd(s_gn + 32 + cib + j, s2v[j]);
        }
    }

    int hl = wid >> 1;            // output row within tile (0..7)
    int wbase = (wid & 1) * 32;   // col base of this warp's 32-pixel strip
    int g = lane >> 2;
    int t = lane & 3;

    const u32 inh_a = smb + SM_INH;
    const u32 wh_a  = smb + SM_WH;
    const u32 alane = (u32)((lane & 15) * 80 + (lane >> 4) * 16);
    const u32 blane = (u32)(((lane >> 4) * 8 + (lane & 7)) * 656 + ((lane >> 3) & 1) * 16);

    float acc[2][4][4];
    for (int m = 0; m < 2; m++)
        for (int n = 0; n < 4; n++)
            for (int r = 0; r < 4; r++) acc[m][n][r] = 0.f;

    for (int tap = 0; tap < 9; tap++) {
        int kh = tap / 3;
        int kw = tap - kh*3;
        u32 apix = inh_a + (u32)(((hl + kh)*66 + wbase + kw) * 80) + alane;
        u32 wtap = wh_a + blane + (u32)(tap * 64);
        #pragma unroll
        for (int c = 0; c < 2; c++) {
            u32 aoff = apix + (u32)(c * 32);
            u32 boff = wtap + (u32)(c * 32);
            u32 ah0[4], ah1[4];
            ldsm_x4(ah0, aoff);
            ldsm_x4(ah1, aoff + 1280u);
            u32 bh[2][4];
            ldsm_x4(bh[0], boff);
            ldsm_x4(bh[1], boff + 10496u);
            #pragma unroll
            for (int n = 0; n < 4; n++) {
                const u32* Bh = &bh[n >> 1][(n & 1) * 2];
                mma_f16(acc[0][n], ah0, Bh);
                mma_f16(acc[1][n], ah1, Bh);
            }
        }
    }
    // all input-plane reads done before s_out alias is written
    __syncthreads();

    // stage D to smem: s_out[pix_in_tile * 33 + ch]
    #pragma unroll
    for (int m = 0; m < 2; m++) {
        #pragma unroll
        for (int n = 0; n < 4; n++) {
            int pix0 = hl*64 + wbase + m*16 + g;
            int ch = n*8 + 2*t;
            s_out[pix0*33 + ch]       = acc[m][n][0];
            s_out[pix0*33 + ch + 1]   = acc[m][n][1];
            s_out[(pix0+8)*33 + ch]   = acc[m][n][2];
            s_out[(pix0+8)*33 + ch+1] = acc[m][n][3];
        }
    }
    __syncwarp();

    // x2 write as fp16 (+b3) + channel sums from fp32 (lane = channel)
    float b3v = b3[lane];
    float csum = 0.f;
    int hglob = h0 + hl;
    for (int j2 = 0; j2 < 32; j2++) {
        int pix = hl*64 + wbase + j2;
        float v = s_out[pix*33 + lane] + b3v;
        g_x2h[((size_t)gimg*4096 + (size_t)hglob*64 + wbase + j2)*32 + lane] = __float2half_rn(v);
        csum += v;
    }

    s_red[wid*32 + lane] = csum;
    __syncthreads();
    if (wid == 0) {
        float tsum = 0.f;
        for (int k = 0; k < 16; k++) tsum += s_red[k*32 + lane];
        atomicAdd(g_colsum + gimg*32 + lane, tsum);
    } else if (wid == 1) {
        atomicAdd(g_sum + gimg*32 + lane, s_gn[lane]);
    } else if (wid == 2) {
        atomicAdd(g_sumsq + gimg*32 + lane, s_gn[32 + lane]);
    }
}

// ===================== K3: mu/rsqrt, softmax(x21), softmax(gn_beta)=x11 =====================
__global__ void k3_finalize(const float* __restrict__ gn_beta) {
    int g = blockIdx.x;
    int t = threadIdx.x;
    float mu  = g_sum[g*32 + t] * (1.f/4096.f);
    float var = g_sumsq[g*32 + t] * (1.f/4096.f) - mu*mu;
    g_mu[g*32 + t] = mu;
    g_rs[g*32 + t] = rsqrtf(var + 1e-3f);

    float m = g_colsum[g*32 + t] * (1.f/4096.f);
    float mx = m;
    for (int o = 16; o > 0; o >>= 1) mx = fmaxf(mx, __shfl_xor_sync(0xffffffffu, mx, o));
    float e = expf(m - mx);
    float se = e;
    for (int o = 16; o > 0; o >>= 1) se += __shfl_xor_sync(0xffffffffu, se, o);
    g_x21[g*32 + t] = e / se;

    if (g == 0) {
        float bb = gn_beta[t];
        float mx2 = bb;
        for (int o = 16; o > 0; o >>= 1) mx2 = fmaxf(mx2, __shfl_xor_sync(0xffffffffu, mx2, o));
        float e2 = expf(bb - mx2);
        float s2 = e2;
        for (int o = 16; o > 0; o >>= 1) s2 += __shfl_xor_sync(0xffffffffu, s2, o);
        g_x11[t] = e2 / s2;
    }
}

// ===================== K4: weights (flat einsum) + sigmoid + output =====================
__global__ void __launch_bounds__(1024) k4_weights_out(const float* __restrict__ x,
                                                       const float* __restrict__ gn_gamma,
                                                       const float* __restrict__ gn_beta,
                                                       float* __restrict__ out) {
    int g = blockIdx.x;
    int tid = threadIdx.x;
    const float* A   = x     + (size_t)g * IMG_ELEMS;
    const __half* X2 = g_x2h + (size_t)g * IMG_ELEMS;
    __shared__ float s_wt[4096];
    __shared__ float s_sh[2048];
    __shared__ float s_sw[2048];
    __shared__ float s_x11[32];
    __shared__ float s_x21[32];
    __shared__ float s_mu[32];
    __shared__ float s_rs[32];
    __shared__ float s_gb[64];
    for (int i = tid; i < 2048; i += 1024) {
        s_sh[i] = g_sh[g*2048 + i];
        s_sw[i] = g_sw[g*2048 + i];
    }
    if (tid < 32) {
        s_x11[tid] = g_x11[tid];
        s_x21[tid] = g_x21[g*32 + tid];
        s_mu[tid]  = g_mu[g*32 + tid];
        s_rs[tid]  = g_rs[g*32 + tid];
        s_gb[tid]      = gn_gamma[tid];
        s_gb[32 + tid] = gn_beta[tid];
    }
    __syncthreads();

    for (int k = 0; k < 4; k++) {
        int l  = tid + k*1024;
        int cc = l & 31;
        int q  = l >> 5;
        int w  = q & 63;
        float rs = s_rs[cc];
        float mu = s_mu[cc];
        float gam = s_gb[cc];
        float bet = s_gb[32 + cc];
        float swv = s_sw[w*32 + cc];
        float acc = 0.f;
        for (int c = 0; c < 32; c++) {
            int f = c*4096 + l;
            float x2v = __half2float(X2[f]);
            float a   = A[f];
            int h = 2*c + (q >> 6);
            float gt  = a * s_sh[h*32 + cc] * swv;
            float x1v = (gt - mu) * rs * gam + bet;
            acc += s_x11[c]*x2v + s_x21[c]*x1v;
        }
        s_wt[l] = 1.f / (1.f + expf(-acc));
    }
    __syncthreads();

    const float4* A4 = (const float4*)A;
    float4* O4 = (float4*)(out + (size_t)g * IMG_ELEMS);
    for (int i = tid; i < IMG_ELEMS/4; i += 1024) {
        float sg = s_wt[i >> 3];
        float4 a4 = A4[i];
        float4 o;
        o.x = a4.x*sg;
        o.y = a4.y*sg;
        o.z = a4.z*sg;
        o.w = a4.w*sg;
        O4[i] = o;
    }
}

// ===================== launch =====================
extern "C" void kernel_launch(void* const* d_in, const int* in_sizes, int n_in,
                              void* d_out, int out_size) {
    const float* x     = (const float*)d_in[0];
    const float* w1    = (const float*)d_in[1];
    const float* b1    = (const float*)d_in[2];
    const float* w3    = (const float*)d_in[3];
    const float* b3    = (const float*)d_in[4];
    const float* gamma = (const float*)d_in[5];
    const float* beta  = (const float*)d_in[6];
    float* out = (float*)d_out;

    cudaFuncSetAttribute(k2_conv, cudaFuncAttributeMaxDynamicSharedMemorySize, SM_TOTAL);

    k0_prep<<<1, 256>>>(w3);
    k1_means<<<NIMG, 256>>>(x, w1, b1);
    k2_conv<<<dim3(8, NIMG), 512, SM_TOTAL>>>(x, b3);
    k3_finalize<<<NIMG, 32>>>(beta);
    k4_weights_out<<<NIMG, 1024>>>(x, gamma, beta, out);
}

// round 16
// speedup vs baseline: 1.0760x; 1.0760x over previous
#include <cuda_runtime.h>
#include <cuda_fp16.h>
#include <cstdint>
#include <math.h>

typedef unsigned int u32;

#define NIMG 512
#define IMG_ELEMS (64*64*32)

// ---- scratch (device globals; allocation-free rule) ----
__device__ __half g_x2h[67108864];      // conv output (+b3), fp16
__device__ float g_sh[NIMG*64*32];
__device__ float g_sw[NIMG*64*32];
__device__ float g_sum[NIMG*32];
__device__ float g_sumsq[NIMG*32];
__device__ float g_colsum[NIMG*32];
// W transposed [d][k], fp16, row stride 328 halves (=656 B; ldmatrix conflict-free)
__device__ __align__(16) unsigned short g_whi[32*328];

// m16n8k16 row.col fp16 -> f32 accumulate (HMMA.16816; valid on base sm_103)
__device__ __forceinline__ void mma_f16(float* c, const u32* a, const u32* b) {
    asm volatile("mma.sync.aligned.m16n8k16.row.col.f32.f16.f16.f32 {%0,%1,%2,%3}, {%4,%5,%6,%7}, {%8,%9}, {%0,%1,%2,%3};" : "+f"(c[0]), "+f"(c[1]), "+f"(c[2]), "+f"(c[3]) : "r"(a[0]), "r"(a[1]), "r"(a[2]), "r"(a[3]), "r"(b[0]), "r"(b[1]));
}
__device__ __forceinline__ void ldsm_x4(u32* r, u32 saddr) {
    asm volatile("ldmatrix.sync.aligned.m8n8.x4.shared.b16 {%0,%1,%2,%3}, [%4];" : "=r"(r[0]), "=r"(r[1]), "=r"(r[2]), "=r"(r[3]) : "r"(saddr));
}
__device__ __forceinline__ u32 smem_u32(const void* p) {
    u32 a;
    asm("{ .reg .u64 t; cvta.to.shared.u64 t, %1; cvt.u32.u64 %0, t; }" : "=r"(a) : "l"(p));
    return a;
}

// ===================== K1: row/col means + 32x32 matmul + sigmoid (+ zero stats, + W prep on block 0) =====================
__global__ void __launch_bounds__(256) k1_means(const float* __restrict__ x,
                                                const float* __restrict__ w1,
                                                const float* __restrict__ b1,
                                                const float* __restrict__ w3) {
    int g = blockIdx.x;
    const float* A = x + (size_t)g * IMG_ELEMS;
    __shared__ float s_xh[2048];
    __shared__ float s_xw[2048];
    __shared__ float s_w1[1024];
    int tid = threadIdx.x;
    int lane = tid & 31;
    int wid = tid >> 5;

    if (g == 0) {  // merged k0: transpose conv weights to fp16
        for (int idx = tid; idx < 32*328; idx += 256) {
            int d = idx / 328;
            int k = idx % 328;
            float v = (k < 288) ? w3[k*32 + d] : 0.f;
            __half hb = __float2half_rn(v);
            g_whi[idx] = *(unsigned short*)&hb;
        }
    }
    if (tid < 32) {
        g_sum[g*32+tid] = 0.f;
        g_sumsq[g*32+tid] = 0.f;
        g_colsum[g*32+tid] = 0.f;
    }
    for (int i = tid; i < 1024; i += 256) s_w1[i] = w1[i];

    for (int h = wid; h < 64; h += 8) {
        float acc = 0.f;
        for (int w = 0; w < 64; w++) acc += A[(h*64 + w)*32 + lane];
        s_xh[h*32 + lane] = acc * (1.f/64.f);
    }
    for (int w = wid; w < 64; w += 8) {
        float acc = 0.f;
        for (int h = 0; h < 64; h++) acc += A[(h*64 + w)*32 + lane];
        s_xw[w*32 + lane] = acc * (1.f/64.f);
    }
    __syncthreads();
    for (int i = tid; i < 4096; i += 256) {
        int row = i >> 5;
        int d = i & 31;
        const float* v = (row < 64) ? (s_xh + row*32) : (s_xw + (row-64)*32);
        float acc = b1[d];
        for (int c = 0; c < 32; c++) acc = fmaf(v[c], s_w1[c*32 + d], acc);
        float s = 1.f / (1.f + expf(-acc));
        if (row < 64) g_sh[(g*64 + row)*32 + d] = s;
        else g_sw[(g*64 + (row-64))*32 + d] = s;
    }
}

// ===================== K2: fp16 HMMA conv, stats fused into fill (R14 config) =====================
// Block: 4 output rows x 64 cols x 32ch. 8 warps; warp = 32-pixel strip.
// s_out stride 33 -> smem 56064 B -> 4 CTAs/SM. Fill loop r-outer (no int division).
#define SM_WH  0
#define SM_INH 20992
#define SM_RED 54784
#define SM_GN  55808
#define SM_TOTAL 56064
// input plane: [6 rows][66 cols][32 ci fp16], col stride 20 u32 (80 B); 31680 B
// s_out alias: 256 px * 33 f32 = 33792 B (region is max of the two)

__global__ void __launch_bounds__(256, 4) k2_conv(const float* __restrict__ x,
                                                  const float* __restrict__ b3) {
    int gimg = blockIdx.y;
    int h0 = blockIdx.x * 4;
    const float* A = x + (size_t)gimg * IMG_ELEMS;
    extern __shared__ char sm[];
    u32 smb = smem_u32(sm);
    u32* inh32 = (u32*)(sm + SM_INH);
    float* s_out = (float*)(sm + SM_INH);   // alias: valid only after all input reads; 33792 B
    float* s_red = (float*)(sm + SM_RED);
    float* s_gn  = (float*)(sm + SM_GN);    // [0..31] sum, [32..63] sumsq
    int tid = threadIdx.x;
    int lane = tid & 31;
    int wid = tid >> 5;

    if (tid < 64) s_gn[tid] = 0.f;
    {
        const float4* srcH = (const float4*)g_whi;
        float4* dstH = (float4*)(sm + SM_WH);
        for (int i = tid; i < 1312; i += 256) dstH[i] = srcH[i];
    }

    float s1v[4] = {0.f, 0.f, 0.f, 0.f};
    float s2v[4] = {0.f, 0.f, 0.f, 0.f};
    for (int r = 0; r < 6; r++) {
        int h = h0 - 1 + r;
        bool hok = (h >= 0 && h < 64);
        for (int j = tid; j < 528; j += 256) {     // 66 cols x 8 ci-chunks
            int col = j >> 3;
            int ci = (j & 7) * 4;
            bool inb = hok && col >= 1 && col <= 64;
            float4 v = make_float4(0.f, 0.f, 0.f, 0.f);
            if (inb) v = *(const float4*)(A + (h*64 + col - 1)*32 + ci);
            __half2 p01 = __floats2half2_rn(v.x, v.y);
            __half2 p23 = __floats2half2_rn(v.z, v.w);
            int wb = (r*66 + col)*20 + (ci >> 1);
            inh32[wb]     = *(u32*)&p01;
            inh32[wb + 1] = *(u32*)&p23;
            if (inb && r >= 1 && r <= 4) {
                float4 shv = *(const float4*)(g_sh + (gimg*64 + h)*32 + ci);
                float4 swv = *(const float4*)(g_sw + (gimg*64 + col - 1)*32 + ci);
                float g0 = v.x * shv.x * swv.x;
                float g1 = v.y * shv.y * swv.y;
                float g2 = v.z * shv.z * swv.z;
                float g3 = v.w * shv.w * swv.w;
                s1v[0] += g0; s2v[0] += g0*g0;
                s1v[1] += g1; s2v[1] += g1*g1;
                s1v[2] += g2; s2v[2] += g2*g2;
                s1v[3] += g3; s2v[3] += g3*g3;
            }
        }
    }
    __syncthreads();

    #pragma unroll
    for (int j = 0; j < 4; j++) {
        s1v[j] += __shfl_xor_sync(0xffffffffu, s1v[j], 8);
        s1v[j] += __shfl_xor_sync(0xffffffffu, s1v[j], 16);
        s2v[j] += __shfl_xor_sync(0xffffffffu, s2v[j], 8);
        s2v[j] += __shfl_xor_sync(0xffffffffu, s2v[j], 16);
    }
    if (lane < 8) {
        int cib = (lane & 7) * 4;
        #pragma unroll
        for (int j = 0; j < 4; j++) {
            atomicAdd(s_gn + cib + j, s1v[j]);
            atomicAdd(s_gn + 32 + cib + j, s2v[j]);
        }
    }

    int hl = wid >> 1;
    int wbase = (wid & 1) * 32;
    int g = lane >> 2;
    int t = lane & 3;

    const u32 inh_a = smb + SM_INH;
    const u32 wh_a  = smb + SM_WH;
    const u32 alane = (u32)((lane & 15) * 80 + (lane >> 4) * 16);
    const u32 blane = (u32)(((lane >> 4) * 8 + (lane & 7)) * 656 + ((lane >> 3) & 1) * 16);

    float acc[2][4][4];
    for (int m = 0; m < 2; m++)
        for (int n = 0; n < 4; n++)
            for (int r = 0; r < 4; r++) acc[m][n][r] = 0.f;

    for (int tap = 0; tap < 9; tap++) {
        int kh = tap / 3;
        int kw = tap - kh*3;
        u32 apix = inh_a + (u32)(((hl + kh)*66 + wbase + kw) * 80) + alane;
        u32 wtap = wh_a + blane + (u32)(tap * 64);
        #pragma unroll
        for (int c = 0; c < 2; c++) {
            u32 aoff = apix + (u32)(c * 32);
            u32 boff = wtap + (u32)(c * 32);
            u32 ah0[4], ah1[4];
            ldsm_x4(ah0, aoff);
            ldsm_x4(ah1, aoff + 1280u);
            u32 bh[2][4];
            ldsm_x4(bh[0], boff);
            ldsm_x4(bh[1], boff + 10496u);
            #pragma unroll
            for (int n = 0; n < 4; n++) {
                const u32* Bh = &bh[n >> 1][(n & 1) * 2];
                mma_f16(acc[0][n], ah0, Bh);
                mma_f16(acc[1][n], ah1, Bh);
            }
        }
    }
    __syncthreads();

    #pragma unroll
    for (int m = 0; m < 2; m++) {
        #pragma unroll
        for (int n = 0; n < 4; n++) {
            int pix0 = hl*64 + wbase + m*16 + g;
            int ch = n*8 + 2*t;
            s_out[pix0*33 + ch]       = acc[m][n][0];
            s_out[pix0*33 + ch + 1]   = acc[m][n][1];
            s_out[(pix0+8)*33 + ch]   = acc[m][n][2];
            s_out[(pix0+8)*33 + ch+1] = acc[m][n][3];
        }
    }
    __syncwarp();

    float b3v = b3[lane];
    float csum = 0.f;
    int hglob = h0 + hl;
    for (int j2 = 0; j2 < 32; j2++) {
        int pix = hl*64 + wbase + j2;
        float v = s_out[pix*33 + lane] + b3v;
        g_x2h[((size_t)gimg*4096 + (size_t)hglob*64 + wbase + j2)*32 + lane] = __float2half_rn(v);
        csum += v;
    }

    s_red[wid*32 + lane] = csum;
    __syncthreads();
    if (wid == 0) {
        float tsum = 0.f;
        for (int k = 0; k < 8; k++) tsum += s_red[k*32 + lane];
        atomicAdd(g_colsum + gimg*32 + lane, tsum);
    } else if (wid == 1) {
        atomicAdd(g_sum + gimg*32 + lane, s_gn[lane]);
    } else if (wid == 2) {
        atomicAdd(g_sumsq + gimg*32 + lane, s_gn[32 + lane]);
    }
}

// ===================== K4: stats finalize (merged k3) + weights + sigmoid + output =====================
__global__ void __launch_bounds__(1024) k4_weights_out(const float* __restrict__ x,
                                                       const float* __restrict__ gn_gamma,
                                                       const float* __restrict__ gn_beta,
                                                       float* __restrict__ out) {
    int g = blockIdx.x;
    int tid = threadIdx.x;
    const float* A   = x     + (size_t)g * IMG_ELEMS;
    const __half* X2 = g_x2h + (size_t)g * IMG_ELEMS;
    __shared__ float s_wt[4096];
    __shared__ float s_sh[2048];
    __shared__ float s_sw[2048];
    __shared__ float s_x11[32];
    __shared__ float s_x21[32];
    __shared__ float s_mu[32];
    __shared__ float s_rs[32];
    __shared__ float s_gb[64];
    for (int i = tid; i < 2048; i += 1024) {
        s_sh[i] = g_sh[g*2048 + i];
        s_sw[i] = g_sw[g*2048 + i];
    }
    if (tid < 32) {   // merged k3: finalize stats for this image (warp 0)
        int t = tid;
        float mu  = g_sum[g*32 + t] * (1.f/4096.f);
        float var = g_sumsq[g*32 + t] * (1.f/4096.f) - mu*mu;
        s_mu[t] = mu;
        s_rs[t] = rsqrtf(var + 1e-3f);

        float m = g_colsum[g*32 + t] * (1.f/4096.f);
        float mx = m;
        for (int o = 16; o > 0; o >>= 1) mx = fmaxf(mx, __shfl_xor_sync(0xffffffffu, mx, o));
        float e = expf(m - mx);
        float se = e;
        for (int o = 16; o > 0; o >>= 1) se += __shfl_xor_sync(0xffffffffu, se, o);
        s_x21[t] = e / se;

        float bb = gn_beta[t];
        float mx2 = bb;
        for (int o = 16; o > 0; o >>= 1) mx2 = fmaxf(mx2, __shfl_xor_sync(0xffffffffu, mx2, o));
        float e2 = expf(bb - mx2);
        float s2 = e2;
        for (int o = 16; o > 0; o >>= 1) s2 += __shfl_xor_sync(0xffffffffu, s2, o);
        s_x11[t] = e2 / s2;

        s_gb[t]      = gn_gamma[t];
        s_gb[32 + t] = bb;
    }
    __syncthreads();

    for (int k = 0; k < 4; k++) {
        int l  = tid + k*1024;
        int cc = l & 31;
        int q  = l >> 5;
        int w  = q & 63;
        float rs = s_rs[cc];
        float mu = s_mu[cc];
        float gam = s_gb[cc];
        float bet = s_gb[32 + cc];
        float swv = s_sw[w*32 + cc];
        float acc = 0.f;
        for (int c = 0; c < 32; c++) {
            int f = c*4096 + l;
            float x2v = __half2float(X2[f]);
            float a   = A[f];
            int h = 2*c + (q >> 6);
            float gt  = a * s_sh[h*32 + cc] * swv;
            float x1v = (gt - mu) * rs * gam + bet;
            acc += s_x11[c]*x2v + s_x21[c]*x1v;
        }
        s_wt[l] = 1.f / (1.f + expf(-acc));
    }
    __syncthreads();

    const float4* A4 = (const float4*)A;
    float4* O4 = (float4*)(out + (size_t)g * IMG_ELEMS);
    for (int i = tid; i < IMG_ELEMS/4; i += 1024) {
        float sg = s_wt[i >> 3];
        float4 a4 = A4[i];
        float4 o;
        o.x = a4.x*sg;
        o.y = a4.y*sg;
        o.z = a4.z*sg;
        o.w = a4.w*sg;
        O4[i] = o;
    }
}

// ===================== launch =====================
extern "C" void kernel_launch(void* const* d_in, const int* in_sizes, int n_in,
                              void* d_out, int out_size) {
    const float* x     = (const float*)d_in[0];
    const float* w1    = (const float*)d_in[1];
    const float* b1    = (const float*)d_in[2];
    const float* w3    = (const float*)d_in[3];
    const float* b3    = (const float*)d_in[4];
    const float* gamma = (const float*)d_in[5];
    const float* beta  = (const float*)d_in[6];
    float* out = (float*)d_out;

    cudaFuncSetAttribute(k2_conv, cudaFuncAttributeMaxDynamicSharedMemorySize, SM_TOTAL);

    k1_means<<<NIMG, 256>>>(x, w1, b1, w3);
    k2_conv<<<dim3(16, NIMG), 256, SM_TOTAL>>>(x, b3);
    k4_weights_out<<<NIMG, 1024>>>(x, gamma, beta, out);
}

// round 17
// speedup vs baseline: 1.1534x; 1.0720x over previous
#include <cuda_runtime.h>
#include <cuda_fp16.h>
#include <cstdint>
#include <math.h>

typedef unsigned int u32;

#define NIMG 512
#define IMG_ELEMS (64*64*32)

// ---- scratch (device globals; allocation-free rule) ----
__device__ __half g_x2h[67108864];      // conv output (+b3), fp16
__device__ float g_sh[NIMG*64*32];
__device__ float g_sw[NIMG*64*32];
__device__ float g_sum[NIMG*32];
__device__ float g_sumsq[NIMG*32];
__device__ float g_colsum[NIMG*32];
// W transposed [d][k], fp16, row stride 328 halves (=656 B; ldmatrix conflict-free)
__device__ __align__(16) unsigned short g_whi[32*328];

// m16n8k16 row.col fp16 -> f32 accumulate (HMMA.16816; valid on base sm_103)
__device__ __forceinline__ void mma_f16(float* c, const u32* a, const u32* b) {
    asm volatile("mma.sync.aligned.m16n8k16.row.col.f32.f16.f16.f32 {%0,%1,%2,%3}, {%4,%5,%6,%7}, {%8,%9}, {%0,%1,%2,%3};" : "+f"(c[0]), "+f"(c[1]), "+f"(c[2]), "+f"(c[3]) : "r"(a[0]), "r"(a[1]), "r"(a[2]), "r"(a[3]), "r"(b[0]), "r"(b[1]));
}
__device__ __forceinline__ void ldsm_x4(u32* r, u32 saddr) {
    asm volatile("ldmatrix.sync.aligned.m8n8.x4.shared.b16 {%0,%1,%2,%3}, [%4];" : "=r"(r[0]), "=r"(r[1]), "=r"(r[2]), "=r"(r[3]) : "r"(saddr));
}
__device__ __forceinline__ u32 smem_u32(const void* p) {
    u32 a;
    asm("{ .reg .u64 t; cvta.to.shared.u64 t, %1; cvt.u32.u64 %0, t; }" : "=r"(a) : "l"(p));
    return a;
}

// ===================== K1: SINGLE-PASS row/col sums + 32x32 matmul + sigmoid =====================
// Warp wid owns w-columns [wid*8, wid*8+8), lane = ci. One read of x.
// Col sums: exclusive registers -> s_xw. Row sums: per-(warp,h) partial -> smem atomicAdd.
__global__ void __launch_bounds__(256) k1_means(const float* __restrict__ x,
                                                const float* __restrict__ w1,
                                                const float* __restrict__ b1,
                                                const float* __restrict__ w3) {
    int g = blockIdx.x;
    const float* A = x + (size_t)g * IMG_ELEMS;
    __shared__ float s_xh[2048];
    __shared__ float s_xw[2048];
    __shared__ float s_w1[1024];
    int tid = threadIdx.x;
    int lane = tid & 31;
    int wid = tid >> 5;

    if (g == 0) {  // merged k0: transpose conv weights to fp16
        for (int idx = tid; idx < 32*328; idx += 256) {
            int d = idx / 328;
            int k = idx % 328;
            float v = (k < 288) ? w3[k*32 + d] : 0.f;
            __half hb = __float2half_rn(v);
            g_whi[idx] = *(unsigned short*)&hb;
        }
    }
    if (tid < 32) {
        g_sum[g*32+tid] = 0.f;
        g_sumsq[g*32+tid] = 0.f;
        g_colsum[g*32+tid] = 0.f;
    }
    for (int i = tid; i < 1024; i += 256) s_w1[i] = w1[i];
    for (int i = tid; i < 2048; i += 256) s_xh[i] = 0.f;
    __syncthreads();

    float colacc[8];
    #pragma unroll
    for (int j = 0; j < 8; j++) colacc[j] = 0.f;
    int w0 = wid * 8;
    for (int h = 0; h < 64; h++) {
        float rpart = 0.f;
        #pragma unroll
        for (int j = 0; j < 8; j++) {
            float val = A[(h*64 + w0 + j)*32 + lane];
            colacc[j] += val;
            rpart += val;
        }
        atomicAdd(s_xh + h*32 + lane, rpart);
    }
    #pragma unroll
    for (int j = 0; j < 8; j++) s_xw[(w0 + j)*32 + lane] = colacc[j];
    __syncthreads();

    // 128 rows (64 h + 64 w) x 32 outputs; mean = sum/64; sigmoid; store
    for (int i = tid; i < 4096; i += 256) {
        int row = i >> 5;
        int d = i & 31;
        const float* v = (row < 64) ? (s_xh + row*32) : (s_xw + (row-64)*32);
        float acc = b1[d];
        for (int c = 0; c < 32; c++) acc = fmaf(v[c] * (1.f/64.f), s_w1[c*32 + d], acc);
        float s = 1.f / (1.f + expf(-acc));
        if (row < 64) g_sh[(g*64 + row)*32 + d] = s;
        else g_sw[(g*64 + (row-64))*32 + d] = s;
    }
}

// ===================== K2: fp16 HMMA conv, stats fused into fill (R14 config) =====================
#define SM_WH  0
#define SM_INH 20992
#define SM_RED 54784
#define SM_GN  55808
#define SM_TOTAL 56064
// input plane: [6 rows][66 cols][32 ci fp16], col stride 20 u32 (80 B); 31680 B
// s_out alias: 256 px * 33 f32 = 33792 B (region is max of the two)

__global__ void __launch_bounds__(256, 4) k2_conv(const float* __restrict__ x,
                                                  const float* __restrict__ b3) {
    int gimg = blockIdx.y;
    int h0 = blockIdx.x * 4;
    const float* A = x + (size_t)gimg * IMG_ELEMS;
    extern __shared__ char sm[];
    u32 smb = smem_u32(sm);
    u32* inh32 = (u32*)(sm + SM_INH);
    float* s_out = (float*)(sm + SM_INH);   // alias: valid only after all input reads; 33792 B
    float* s_red = (float*)(sm + SM_RED);
    float* s_gn  = (float*)(sm + SM_GN);    // [0..31] sum, [32..63] sumsq
    int tid = threadIdx.x;
    int lane = tid & 31;
    int wid = tid >> 5;

    if (tid < 64) s_gn[tid] = 0.f;
    {
        const float4* srcH = (const float4*)g_whi;
        float4* dstH = (float4*)(sm + SM_WH);
        for (int i = tid; i < 1312; i += 256) dstH[i] = srcH[i];
    }

    float s1v[4] = {0.f, 0.f, 0.f, 0.f};
    float s2v[4] = {0.f, 0.f, 0.f, 0.f};
    for (int r = 0; r < 6; r++) {
        int h = h0 - 1 + r;
        bool hok = (h >= 0 && h < 64);
        for (int j = tid; j < 528; j += 256) {     // 66 cols x 8 ci-chunks
            int col = j >> 3;
            int ci = (j & 7) * 4;
            bool inb = hok && col >= 1 && col <= 64;
            float4 v = make_float4(0.f, 0.f, 0.f, 0.f);
            if (inb) v = *(const float4*)(A + (h*64 + col - 1)*32 + ci);
            __half2 p01 = __floats2half2_rn(v.x, v.y);
            __half2 p23 = __floats2half2_rn(v.z, v.w);
            int wb = (r*66 + col)*20 + (ci >> 1);
            inh32[wb]     = *(u32*)&p01;
            inh32[wb + 1] = *(u32*)&p23;
            if (inb && r >= 1 && r <= 4) {
                float4 shv = *(const float4*)(g_sh + (gimg*64 + h)*32 + ci);
                float4 swv = *(const float4*)(g_sw + (gimg*64 + col - 1)*32 + ci);
                float g0 = v.x * shv.x * swv.x;
                float g1 = v.y * shv.y * swv.y;
                float g2 = v.z * shv.z * swv.z;
                float g3 = v.w * shv.w * swv.w;
                s1v[0] += g0; s2v[0] += g0*g0;
                s1v[1] += g1; s2v[1] += g1*g1;
                s1v[2] += g2; s2v[2] += g2*g2;
                s1v[3] += g3; s2v[3] += g3*g3;
            }
        }
    }
    __syncthreads();

    #pragma unroll
    for (int j = 0; j < 4; j++) {
        s1v[j] += __shfl_xor_sync(0xffffffffu, s1v[j], 8);
        s1v[j] += __shfl_xor_sync(0xffffffffu, s1v[j], 16);
        s2v[j] += __shfl_xor_sync(0xffffffffu, s2v[j], 8);
        s2v[j] += __shfl_xor_sync(0xffffffffu, s2v[j], 16);
    }
    if (lane < 8) {
        int cib = (lane & 7) * 4;
        #pragma unroll
        for (int j = 0; j < 4; j++) {
            atomicAdd(s_gn + cib + j, s1v[j]);
            atomicAdd(s_gn + 32 + cib + j, s2v[j]);
        }
    }

    int hl = wid >> 1;
    int wbase = (wid & 1) * 32;
    int g = lane >> 2;
    int t = lane & 3;

    const u32 inh_a = smb + SM_INH;
    const u32 wh_a  = smb + SM_WH;
    const u32 alane = (u32)((lane & 15) * 80 + (lane >> 4) * 16);
    const u32 blane = (u32)(((lane >> 4) * 8 + (lane & 7)) * 656 + ((lane >> 3) & 1) * 16);

    float acc[2][4][4];
    for (int m = 0; m < 2; m++)
        for (int n = 0; n < 4; n++)
            for (int r = 0; r < 4; r++) acc[m][n][r] = 0.f;

    for (int tap = 0; tap < 9; tap++) {
        int kh = tap / 3;
        int kw = tap - kh*3;
        u32 apix = inh_a + (u32)(((hl + kh)*66 + wbase + kw) * 80) + alane;
        u32 wtap = wh_a + blane + (u32)(tap * 64);
        #pragma unroll
        for (int c = 0; c < 2; c++) {
            u32 aoff = apix + (u32)(c * 32);
            u32 boff = wtap + (u32)(c * 32);
            u32 ah0[4], ah1[4];
            ldsm_x4(ah0, aoff);
            ldsm_x4(ah1, aoff + 1280u);
            u32 bh[2][4];
            ldsm_x4(bh[0], boff);
            ldsm_x4(bh[1], boff + 10496u);
            #pragma unroll
            for (int n = 0; n < 4; n++) {
                const u32* Bh = &bh[n >> 1][(n & 1) * 2];
                mma_f16(acc[0][n], ah0, Bh);
                mma_f16(acc[1][n], ah1, Bh);
            }
        }
    }
    __syncthreads();

    #pragma unroll
    for (int m = 0; m < 2; m++) {
        #pragma unroll
        for (int n = 0; n < 4; n++) {
            int pix0 = hl*64 + wbase + m*16 + g;
            int ch = n*8 + 2*t;
            s_out[pix0*33 + ch]       = acc[m][n][0];
            s_out[pix0*33 + ch + 1]   = acc[m][n][1];
            s_out[(pix0+8)*33 + ch]   = acc[m][n][2];
            s_out[(pix0+8)*33 + ch+1] = acc[m][n][3];
        }
    }
    __syncwarp();

    float b3v = b3[lane];
    float csum = 0.f;
    int hglob = h0 + hl;
    for (int j2 = 0; j2 < 32; j2++) {
        int pix = hl*64 + wbase + j2;
        float v = s_out[pix*33 + lane] + b3v;
        g_x2h[((size_t)gimg*4096 + (size_t)hglob*64 + wbase + j2)*32 + lane] = __float2half_rn(v);
        csum += v;
    }

    s_red[wid*32 + lane] = csum;
    __syncthreads();
    if (wid == 0) {
        float tsum = 0.f;
        for (int k = 0; k < 8; k++) tsum += s_red[k*32 + lane];
        atomicAdd(g_colsum + gimg*32 + lane, tsum);
    } else if (wid == 1) {
        atomicAdd(g_sum + gimg*32 + lane, s_gn[lane]);
    } else if (wid == 2) {
        atomicAdd(g_sumsq + gimg*32 + lane, s_gn[32 + lane]);
    }
}

// ===================== K4: stats finalize (merged k3) + weights + sigmoid + output =====================
__global__ void __launch_bounds__(1024) k4_weights_out(const float* __restrict__ x,
                                                       const float* __restrict__ gn_gamma,
                                                       const float* __restrict__ gn_beta,
                                                       float* __restrict__ out) {
    int g = blockIdx.x;
    int tid = threadIdx.x;
    const float* A   = x     + (size_t)g * IMG_ELEMS;
    const __half* X2 = g_x2h + (size_t)g * IMG_ELEMS;
    __shared__ float s_wt[4096];
    __shared__ float s_sh[2048];
    __shared__ float s_sw[2048];
    __shared__ float s_x11[32];
    __shared__ float s_x21[32];
    __shared__ float s_mu[32];
    __shared__ float s_rs[32];
    __shared__ float s_gb[64];
    for (int i = tid; i < 2048; i += 1024) {
        s_sh[i] = g_sh[g*2048 + i];
        s_sw[i] = g_sw[g*2048 + i];
    }
    if (tid < 32) {   // merged k3: finalize stats for this image (warp 0)
        int t = tid;
        float mu  = g_sum[g*32 + t] * (1.f/4096.f);
        float var = g_sumsq[g*32 + t] * (1.f/4096.f) - mu*mu;
        s_mu[t] = mu;
        s_rs[t] = rsqrtf(var + 1e-3f);

        float m = g_colsum[g*32 + t] * (1.f/4096.f);
        float mx = m;
        for (int o = 16; o > 0; o >>= 1) mx = fmaxf(mx, __shfl_xor_sync(0xffffffffu, mx, o));
        float e = expf(m - mx);
        float se = e;
        for (int o = 16; o > 0; o >>= 1) se += __shfl_xor_sync(0xffffffffu, se, o);
        s_x21[t] = e / se;

        float bb = gn_beta[t];
        float mx2 = bb;
        for (int o = 16; o > 0; o >>= 1) mx2 = fmaxf(mx2, __shfl_xor_sync(0xffffffffu, mx2, o));
        float e2 = expf(bb - mx2);
        float s2 = e2;
        for (int o = 16; o > 0; o >>= 1) s2 += __shfl_xor_sync(0xffffffffu, s2, o);
        s_x11[t] = e2 / s2;

        s_gb[t]      = gn_gamma[t];
        s_gb[32 + t] = bb;
    }
    __syncthreads();

    for (int k = 0; k < 4; k++) {
        int l  = tid + k*1024;
        int cc = l & 31;
        int q  = l >> 5;
        int w  = q & 63;
        float rs = s_rs[cc];
        float mu = s_mu[cc];
        float gam = s_gb[cc];
        float bet = s_gb[32 + cc];
        float swv = s_sw[w*32 + cc];
        float acc = 0.f;
        for (int c = 0; c < 32; c++) {
            int f = c*4096 + l;
            float x2v = __half2float(X2[f]);
            float a   = A[f];
            int h = 2*c + (q >> 6);
            float gt  = a * s_sh[h*32 + cc] * swv;
            float x1v = (gt - mu) * rs * gam + bet;
            acc += s_x11[c]*x2v + s_x21[c]*x1v;
        }
        s_wt[l] = 1.f / (1.f + expf(-acc));
    }
    __syncthreads();

    const float4* A4 = (const float4*)A;
    float4* O4 = (float4*)(out + (size_t)g * IMG_ELEMS);
    for (int i = tid; i < IMG_ELEMS/4; i += 1024) {
        float sg = s_wt[i >> 3];
        float4 a4 = A4[i];
        float4 o;
        o.x = a4.x*sg;
        o.y = a4.y*sg;
        o.z = a4.z*sg;
        o.w = a4.w*sg;
        O4[i] = o;
    }
}

// ===================== launch =====================
extern "C" void kernel_launch(void* const* d_in, const int* in_sizes, int n_in,
                              void* d_out, int out_size) {
    const float* x     = (const float*)d_in[0];
    const float* w1    = (const float*)d_in[1];
    const float* b1    = (const float*)d_in[2];
    const float* w3    = (const float*)d_in[3];
    const float* b3    = (const float*)d_in[4];
    const float* gamma = (const float*)d_in[5];
    const float* beta  = (const float*)d_in[6];
    float* out = (float*)d_out;

    cudaFuncSetAttribute(k2_conv, cudaFuncAttributeMaxDynamicSharedMemorySize, SM_TOTAL);

    k1_means<<<NIMG, 256>>>(x, w1, b1, w3);
    k2_conv<<<dim3(16, NIMG), 256, SM_TOTAL>>>(x, b3);
    k4_weights_out<<<NIMG, 1024>>>(x, gamma, beta, out);
}